// round 1
// baseline (speedup 1.0000x reference)
#include <cuda_runtime.h>
#include <cstddef>

// ---------------------------------------------------------------------------
// Collapsed model:
//   g[b,f]    = (1/256) * sum over 16x16 patch grid of x    (f = c*256+pi*16+pj)
//   root[b,d] = sum_f W_emb[d,f]*g[b,f] + b_emb[d] + pos4[d]
//   out[b,o]  = sum_d W_cls[o,d]*root[b,d] + b_cls[o]
// ---------------------------------------------------------------------------

__device__ float g_scratch[64 * 768];      // 196 KB
__device__ float root_scratch[64 * 128];   // 32 KB

// ---------------------------------------------------------------------------
// Kernel 1: strided pooling of x.  grid (4 row-phases, 3 channels, 64 batch),
// 256 threads.  Thread (rbase = t>>6, c4 = t&63) owns pi = 4*q + rbase and
// float4-column c4; sums 16 rows (pi + 16m).  Warp loads are 512B contiguous.
// Block exclusively owns 4 pi rows -> exact final writes of g, no atomics.
// ---------------------------------------------------------------------------
__global__ __launch_bounds__(256) void k1_pool(const float* __restrict__ x) {
    const int q = blockIdx.x;    // 0..3 row phase
    const int c = blockIdx.y;    // 0..2 channel
    const int b = blockIdx.z;    // 0..63 batch
    const int t = threadIdx.x;
    const int rbase = t >> 6;    // 0..3
    const int c4 = t & 63;       // float4 column 0..63
    const int pi = q * 4 + rbase;

    const float4* plane =
        reinterpret_cast<const float4*>(x + ((size_t)(b * 3 + c) << 16));

    float4 acc = make_float4(0.f, 0.f, 0.f, 0.f);
#pragma unroll
    for (int m = 0; m < 16; m++) {
        float4 v = plane[(pi + 16 * m) * 64 + c4];
        acc.x += v.x; acc.y += v.y; acc.z += v.z; acc.w += v.w;
    }

    __shared__ float4 s[4][64];
    s[rbase][c4] = acc;
    __syncthreads();

    if (t < 16) {
        const int rb = t >> 2;   // 0..3
        const int qq = t & 3;    // pj quad 0..3
        float4 sum = make_float4(0.f, 0.f, 0.f, 0.f);
#pragma unroll
        for (int j = 0; j < 16; j++) {
            float4 v = s[rb][qq + 4 * j];
            sum.x += v.x; sum.y += v.y; sum.z += v.z; sum.w += v.w;
        }
        const float sc = 1.0f / 256.0f;
        const int pi2 = q * 4 + rb;
        float4* gout = reinterpret_cast<float4*>(
            g_scratch + b * 768 + c * 256 + pi2 * 16 + qq * 4);
        *gout = make_float4(sum.x * sc, sum.y * sc, sum.z * sc, sum.w * sc);
    }
}

// ---------------------------------------------------------------------------
// Kernel 2: root = g @ W_emb^T + (b_emb + pos4).
// grid (8 d-tiles, 16 b-tiles), 128 threads (4 warps).  Each warp does 4 d's,
// k=768 split over lanes (24 regs of g per batch, 4 batches), shfl-reduce.
// W_emb read coalesced from L2, re-read only 16x (6.3 MB total).
// ---------------------------------------------------------------------------
__global__ __launch_bounds__(128) void k2_root(const float* __restrict__ W_emb,
                                               const float* __restrict__ b_emb,
                                               const float* __restrict__ pos4) {
    const int dt = blockIdx.x;   // 0..7
    const int bt = blockIdx.y;   // 0..15
    const int t = threadIdx.x;
    const int wid = t >> 5;
    const int lane = t & 31;

    float greg[4][24];
#pragma unroll
    for (int j = 0; j < 4; j++) {
        const float* gp = g_scratch + (bt * 4 + j) * 768 + lane;
#pragma unroll
        for (int i = 0; i < 24; i++) greg[j][i] = gp[i * 32];
    }

#pragma unroll
    for (int dd = 0; dd < 4; dd++) {
        const int d = dt * 16 + wid * 4 + dd;
        const float* wp = W_emb + d * 768 + lane;
        float a0 = 0.f, a1 = 0.f, a2 = 0.f, a3 = 0.f;
#pragma unroll
        for (int i = 0; i < 24; i++) {
            float w = wp[i * 32];
            a0 += w * greg[0][i];
            a1 += w * greg[1][i];
            a2 += w * greg[2][i];
            a3 += w * greg[3][i];
        }
#pragma unroll
        for (int off = 16; off >= 1; off >>= 1) {
            a0 += __shfl_xor_sync(0xffffffffu, a0, off);
            a1 += __shfl_xor_sync(0xffffffffu, a1, off);
            a2 += __shfl_xor_sync(0xffffffffu, a2, off);
            a3 += __shfl_xor_sync(0xffffffffu, a3, off);
        }
        if (lane == 0) {
            const float bias = b_emb[d] + pos4[d];
            root_scratch[(bt * 4 + 0) * 128 + d] = a0 + bias;
            root_scratch[(bt * 4 + 1) * 128 + d] = a1 + bias;
            root_scratch[(bt * 4 + 2) * 128 + d] = a2 + bias;
            root_scratch[(bt * 4 + 3) * 128 + d] = a3 + bias;
        }
    }
}

// ---------------------------------------------------------------------------
// Kernel 3: out = root @ W_cls^T + b_cls.
// grid (32 o-tiles, 8 b-tiles), 128 threads.  Warp does 8 o's; root for 8
// batches held in registers (32 regs), k=128 over lanes, shfl-reduce.
// ---------------------------------------------------------------------------
__global__ __launch_bounds__(128) void k3_logits(const float* __restrict__ W_cls,
                                                 const float* __restrict__ b_cls,
                                                 float* __restrict__ out) {
    const int ot = blockIdx.x;   // 0..31
    const int bt = blockIdx.y;   // 0..7
    const int t = threadIdx.x;
    const int wid = t >> 5;
    const int lane = t & 31;

    float rreg[8][4];
#pragma unroll
    for (int j = 0; j < 8; j++) {
        const float* rp = root_scratch + (bt * 8 + j) * 128 + lane;
#pragma unroll
        for (int i = 0; i < 4; i++) rreg[j][i] = rp[i * 32];
    }

#pragma unroll
    for (int oo = 0; oo < 8; oo++) {
        const int o = ot * 32 + wid * 8 + oo;
        if (o < 1000) {
            const float* wp = W_cls + o * 128 + lane;
            float acc[8];
#pragma unroll
            for (int j = 0; j < 8; j++) acc[j] = 0.f;
#pragma unroll
            for (int i = 0; i < 4; i++) {
                float w = wp[i * 32];
#pragma unroll
                for (int j = 0; j < 8; j++) acc[j] += w * rreg[j][i];
            }
#pragma unroll
            for (int off = 16; off >= 1; off >>= 1) {
#pragma unroll
                for (int j = 0; j < 8; j++)
                    acc[j] += __shfl_xor_sync(0xffffffffu, acc[j], off);
            }
            if (lane == 0) {
                const float bc = b_cls[o];
#pragma unroll
                for (int j = 0; j < 8; j++)
                    out[(bt * 8 + j) * 1000 + o] = acc[j] + bc;
            }
        }
    }
}

// ---------------------------------------------------------------------------
// Inputs (metadata order): 0:x 1:W_emb 2:b_emb 3:pos0 4:pos1 5:pos2 6:pos3
//                          7:pos4 8:W_cls 9:b_cls.  Output: (64,1000) f32.
// ---------------------------------------------------------------------------
extern "C" void kernel_launch(void* const* d_in, const int* in_sizes, int n_in,
                              void* d_out, int out_size) {
    const float* x     = (const float*)d_in[0];
    const float* W_emb = (const float*)d_in[1];
    const float* b_emb = (const float*)d_in[2];
    const float* pos4  = (const float*)d_in[7];
    const float* W_cls = (const float*)d_in[8];
    const float* b_cls = (const float*)d_in[9];
    float* out = (float*)d_out;

    k1_pool<<<dim3(4, 3, 64), 256>>>(x);
    k2_root<<<dim3(8, 16), 128>>>(W_emb, b_emb, pos4);
    k3_logits<<<dim3(32, 8), 128>>>(W_cls, b_cls, out);
}